// round 1
// baseline (speedup 1.0000x reference)
#include <cuda_runtime.h>
#include <math.h>

// Problem dims (fixed by the dataset)
constexpr int Nn  = 4000;
constexpr int Ee  = 50000;
constexpr int NGg = 12;
constexpr int Hh  = 128;
constexpr int BDd = 128;
constexpr int Ll  = 2;
constexpr int Bb  = 100;

constexpr int EROWS = Ee * NGg;     // 600000
constexpr int NROWS = Nn * NGg;     // 48000

// ---------------- scratch (device globals; no cudaMalloc allowed) -------------
__device__ __align__(16) float g_grid_node[Nn * NGg * 3];
__device__ __align__(16) float g_eipoly[EROWS * 12];
__device__ __align__(16) float g_bufA[EROWS * BDd];      // h1, then kern
__device__ __align__(16) float g_basis[EROWS * BDd];
__device__ __align__(16) float g_x  [NROWS * Hh];
__device__ __align__(16) float g_x1 [NROWS * Hh];
__device__ __align__(16) float g_x2 [NROWS * Hh];
__device__ __align__(16) float g_ffh[NROWS * 4 * Hh];
__device__ __align__(16) float g_fipoly[NGg * NGg * 2];
__device__ __align__(16) float g_fh1   [NGg * NGg * Hh];
__device__ __align__(16) float g_fbasis[NGg * NGg * BDd];
__device__ __align__(16) float g_fk    [NGg * NGg * Hh];
__device__ float g_gsum[Bb * 4];   // per-graph: sum_x, sum_y, sum_z, count

__device__ __forceinline__ float gelu_f(float x) {
    return 0.5f * x * (1.0f + erff(x * 0.70710678118654752f));
}

// ---------------- tiny kernels -------------------------------------------------
__global__ void k_zero(float* p, int n) {
    int i = blockIdx.x * blockDim.x + threadIdx.x;
    if (i < n) p[i] = 0.f;
}

__global__ void k_gsum(const float* __restrict__ pos, const int* __restrict__ batch) {
    int n = blockIdx.x * blockDim.x + threadIdx.x;
    if (n >= Nn) return;
    int b = batch[n];
    atomicAdd(&g_gsum[b * 4 + 0], pos[n * 3 + 0]);
    atomicAdd(&g_gsum[b * 4 + 1], pos[n * 3 + 1]);
    atomicAdd(&g_gsum[b * 4 + 2], pos[n * 3 + 2]);
    atomicAdd(&g_gsum[b * 4 + 3], 1.f);
}

__global__ void k_grid_node(const int* __restrict__ batch,
                            const float* __restrict__ grid0,
                            const float* __restrict__ R) {
    int idx = blockIdx.x * blockDim.x + threadIdx.x;  // n*NG + k
    if (idx >= Nn * NGg) return;
    int n = idx / NGg, k = idx % NGg;
    const float* Rb = R + batch[n] * 9;
    float gx = grid0[k * 3 + 0], gy = grid0[k * 3 + 1], gz = grid0[k * 3 + 2];
    float* o = g_grid_node + idx * 3;
    o[0] = Rb[0] * gx + Rb[1] * gy + Rb[2] * gz;
    o[1] = Rb[3] * gx + Rb[4] * gy + Rb[5] * gz;
    o[2] = Rb[6] * gx + Rb[7] * gy + Rb[8] * gz;
}

__global__ void k_eipoly(const float* __restrict__ pos,
                         const float* __restrict__ charges,
                         const int* __restrict__ eidx) {
    int idx = blockIdx.x * blockDim.x + threadIdx.x;  // e*NG + k
    if (idx >= EROWS) return;
    int e = idx / NGg, k = idx % NGg;
    int s = eidx[e], d = eidx[Ee + e];
    float rx = pos[s * 3 + 0] - pos[d * 3 + 0];
    float ry = pos[s * 3 + 1] - pos[d * 3 + 1];
    float rz = pos[s * 3 + 2] - pos[d * 3 + 2];
    const float* g = g_grid_node + (s * NGg + k) * 3;
    float inv1 = rx * g[0] + ry * g[1] + rz * g[2];
    float vx = rx - inv1 * g[0], vy = ry - inv1 * g[1], vz = rz - inv1 * g[2];
    float inv2 = sqrtf(vx * vx + vy * vy + vz * vz);
    float cp = charges[s] * charges[d];
    float e0 = inv1, e1 = inv2, e2 = cp;
    float* o = g_eipoly + (size_t)idx * 12;
    o[0] = e0;  o[1] = e1;  o[2] = e2;
    o[3] = e0 * e0; o[4]  = e0 * e1; o[5]  = e0 * e2;
    o[6] = e1 * e0; o[7]  = e1 * e1; o[8]  = e1 * e2;
    o[9] = e2 * e0; o[10] = e2 * e1; o[11] = e2 * e2;
}

__global__ void k_fipoly(const float* __restrict__ grid0) {
    int idx = threadIdx.x;
    if (idx >= NGg * NGg) return;
    int p = idx / NGg, o = idx % NGg;
    float fi = grid0[p * 3 + 0] * grid0[o * 3 + 0] +
               grid0[p * 3 + 1] * grid0[o * 3 + 1] +
               grid0[p * 3 + 2] * grid0[o * 3 + 2];
    g_fipoly[idx * 2 + 0] = fi;
    g_fipoly[idx * 2 + 1] = fi * fi;
}

// naive GEMM for tiny fiber matrices (M=144)
__global__ void k_small_gemm(const float* __restrict__ A, const float* __restrict__ W,
                             const float* __restrict__ bias, float* __restrict__ C,
                             int M, int N, int K, int act) {
    int idx = blockIdx.x * blockDim.x + threadIdx.x;
    if (idx >= M * N) return;
    int r = idx / N, c = idx % N;
    float acc = bias ? bias[c] : 0.f;
    for (int k = 0; k < K; k++) acc = fmaf(A[r * K + k], W[k * N + c], acc);
    C[idx] = act ? gelu_f(acc) : acc;
}

__global__ void k_embed(const float* __restrict__ pos, const float* __restrict__ vel,
                        const float* __restrict__ charges, const int* __restrict__ batch,
                        const float* __restrict__ We) {
    int nk = blockIdx.x;           // n*NG + k
    int h = threadIdx.x;           // 0..127
    int n = nk / NGg;
    const float* g = g_grid_node + nk * 3;
    float vx = vel[n * 3 + 0], vy = vel[n * 3 + 1], vz = vel[n * 3 + 2];
    int b = batch[n];
    float cnt = fmaxf(g_gsum[b * 4 + 3], 1.f);
    float rpx = pos[n * 3 + 0] - g_gsum[b * 4 + 0] / cnt;
    float rpy = pos[n * 3 + 1] - g_gsum[b * 4 + 1] / cnt;
    float rpz = pos[n * 3 + 2] - g_gsum[b * 4 + 2] / cnt;
    float f0 = vx * g[0] + vy * g[1] + vz * g[2];
    float f1 = rpx * g[0] + rpy * g[1] + rpz * g[2];
    float f2 = charges[n];
    float f3 = sqrtf(vx * vx + vy * vy + vz * vz);
    g_x[(size_t)nk * Hh + h] =
        f0 * We[h] + f1 * We[Hh + h] + f2 * We[2 * Hh + h] + f3 * We[3 * Hh + h];
}

// x1[dst,k,:] += x[src,k,:] * kern[e,k,:]
__global__ void k_scatter(const int* __restrict__ eidx) {
    constexpr int HV = Hh / 4;     // 32
    int idx = blockIdx.x * blockDim.x + threadIdx.x;
    if (idx >= Ee * NGg * HV) return;
    int e = idx / (NGg * HV);
    int r = idx % (NGg * HV);
    int k = r / HV, h4 = r % HV;
    int s = eidx[e], d = eidx[Ee + e];
    float4 xv = *reinterpret_cast<const float4*>(&g_x[((size_t)(s * NGg + k)) * Hh + h4 * 4]);
    float4 kv = *reinterpret_cast<const float4*>(&g_bufA[((size_t)(e * NGg + k)) * Hh + h4 * 4]);
    float* o = &g_x1[((size_t)(d * NGg + k)) * Hh + h4 * 4];
    atomicAdd(o + 0, xv.x * kv.x);
    atomicAdd(o + 1, xv.y * kv.y);
    atomicAdd(o + 2, xv.z * kv.z);
    atomicAdd(o + 3, xv.w * kv.w);
}

// x2[n,p,c] = (1/NG) sum_o x1[n,o,c]*fk[p,o,c] + b_conv[c]; then LayerNorm over c
__global__ void k_fiber_ln(const float* __restrict__ bconv, const float* __restrict__ gamma,
                           const float* __restrict__ beta) {
    int np = blockIdx.x;           // n*NG + p
    int n = np / NGg, p = np % NGg;
    int c = threadIdx.x;
    float acc = 0.f;
#pragma unroll
    for (int o = 0; o < NGg; o++)
        acc = fmaf(g_x1[((size_t)(n * NGg + o)) * Hh + c],
                   g_fk[((size_t)(p * NGg + o)) * Hh + c], acc);
    float v = acc * (1.0f / NGg) + bconv[c];

    __shared__ float red[4];
    float s = v;
#pragma unroll
    for (int off = 16; off > 0; off >>= 1) s += __shfl_down_sync(0xffffffffu, s, off);
    if ((c & 31) == 0) red[c >> 5] = s;
    __syncthreads();
    float mean = (red[0] + red[1] + red[2] + red[3]) * (1.f / Hh);
    __syncthreads();
    float dd = v - mean;
    s = dd * dd;
#pragma unroll
    for (int off = 16; off > 0; off >>= 1) s += __shfl_down_sync(0xffffffffu, s, off);
    if ((c & 31) == 0) red[c >> 5] = s;
    __syncthreads();
    float var = (red[0] + red[1] + red[2] + red[3]) * (1.f / Hh);
    g_x2[(size_t)np * Hh + c] = dd * rsqrtf(var + 1e-5f) * gamma[c] + beta[c];
}

// out[n,d] = (1/NG) sum_k grid_node[n,k,d] * (t[n,k,:]·W_ro2 + b_ro2)
__global__ void k_output(const float* __restrict__ Wro2, const float* __restrict__ bro2,
                         float* __restrict__ out) {
    int n = blockIdx.x;
    int h = threadIdx.x;
    __shared__ float red[4];
    __shared__ float ybc;
    float a0 = 0.f, a1 = 0.f, a2 = 0.f;
    for (int k = 0; k < NGg; k++) {
        float s = g_ffh[((size_t)(n * NGg + k)) * Hh + h] * Wro2[h];
#pragma unroll
        for (int off = 16; off > 0; off >>= 1) s += __shfl_down_sync(0xffffffffu, s, off);
        if ((h & 31) == 0) red[h >> 5] = s;
        __syncthreads();
        if (h == 0) ybc = red[0] + red[1] + red[2] + red[3] + bro2[0];
        __syncthreads();
        float y = ybc;
        a0 += g_grid_node[(n * NGg + k) * 3 + 0] * y;
        a1 += g_grid_node[(n * NGg + k) * 3 + 1] * y;
        a2 += g_grid_node[(n * NGg + k) * 3 + 2] * y;
        __syncthreads();
    }
    if (h == 0) {
        out[n * 3 + 0] = a0 * (1.f / NGg);
        out[n * 3 + 1] = a1 * (1.f / NGg);
        out[n * 3 + 2] = a2 * (1.f / NGg);
    }
}

// ---------------- main tiled fp32 GEMM: C = [act](A @ Bw + bias) [+= if ACCUM] --
// A: MxK row-major (K % 4 == 0), Bw: KxN row-major, N % 128 == 0.
constexpr int BM = 128, BN = 128, BK = 16, TM = 8, TN = 8;

template <bool GELU, bool ACCUM>
__global__ void __launch_bounds__(256, 2) gemm_k(
    const float* __restrict__ A, const float* __restrict__ Bw,
    const float* __restrict__ bias, float* __restrict__ C,
    int M, int N, int K) {
    __shared__ float As[BK][BM];
    __shared__ float Bs[BK][BN];
    const int tid = threadIdx.x;
    const int br = blockIdx.x * BM;
    const int bc = blockIdx.y * BN;
    const int tx = tid & 15;
    const int ty = tid >> 4;

    float acc[TM][TN];
#pragma unroll
    for (int i = 0; i < TM; i++)
#pragma unroll
        for (int j = 0; j < TN; j++) acc[i][j] = 0.f;

    const int ktiles = (K + BK - 1) / BK;
    for (int kt = 0; kt < ktiles; kt++) {
        int k0 = kt * BK;
#pragma unroll
        for (int it = 0; it < 2; it++) {          // A tile: 128x16, transposed store
            int f = it * 256 + tid;
            int ar = f >> 2;
            int ac4 = (f & 3) * 4;
            float4 v = make_float4(0.f, 0.f, 0.f, 0.f);
            int gr = br + ar;
            if (gr < M && (k0 + ac4) < K)
                v = *reinterpret_cast<const float4*>(&A[(size_t)gr * K + k0 + ac4]);
            As[ac4 + 0][ar] = v.x;
            As[ac4 + 1][ar] = v.y;
            As[ac4 + 2][ar] = v.z;
            As[ac4 + 3][ar] = v.w;
        }
#pragma unroll
        for (int it = 0; it < 2; it++) {          // B tile: 16x128
            int f = it * 256 + tid;
            int brow = f >> 5;
            int bc4 = (f & 31) * 4;
            float4 v = make_float4(0.f, 0.f, 0.f, 0.f);
            if (k0 + brow < K)
                v = *reinterpret_cast<const float4*>(&Bw[(size_t)(k0 + brow) * N + bc + bc4]);
            *reinterpret_cast<float4*>(&Bs[brow][bc4]) = v;
        }
        __syncthreads();
#pragma unroll
        for (int kk = 0; kk < BK; kk++) {
            float4 a0 = *reinterpret_cast<const float4*>(&As[kk][ty * TM]);
            float4 a1 = *reinterpret_cast<const float4*>(&As[kk][ty * TM + 4]);
            float4 b0 = *reinterpret_cast<const float4*>(&Bs[kk][tx * TN]);
            float4 b1 = *reinterpret_cast<const float4*>(&Bs[kk][tx * TN + 4]);
            float am[8] = {a0.x, a0.y, a0.z, a0.w, a1.x, a1.y, a1.z, a1.w};
            float bn[8] = {b0.x, b0.y, b0.z, b0.w, b1.x, b1.y, b1.z, b1.w};
#pragma unroll
            for (int i = 0; i < TM; i++)
#pragma unroll
                for (int j = 0; j < TN; j++)
                    acc[i][j] = fmaf(am[i], bn[j], acc[i][j]);
        }
        __syncthreads();
    }

    float bv[TN];
#pragma unroll
    for (int j = 0; j < TN; j++) bv[j] = bias ? bias[bc + tx * TN + j] : 0.f;

#pragma unroll
    for (int i = 0; i < TM; i++) {
        int r = br + ty * TM + i;
        if (r >= M) continue;
        float* Cp = &C[(size_t)r * N + bc + tx * TN];
        float vals[TN];
#pragma unroll
        for (int j = 0; j < TN; j++) {
            float v = acc[i][j] + bv[j];
            if (GELU) v = gelu_f(v);
            vals[j] = v;
        }
        if (ACCUM) {
            float4 o0 = *reinterpret_cast<float4*>(Cp);
            float4 o1 = *reinterpret_cast<float4*>(Cp + 4);
            o0.x += vals[0]; o0.y += vals[1]; o0.z += vals[2]; o0.w += vals[3];
            o1.x += vals[4]; o1.y += vals[5]; o1.z += vals[6]; o1.w += vals[7];
            *reinterpret_cast<float4*>(Cp) = o0;
            *reinterpret_cast<float4*>(Cp + 4) = o1;
        } else {
            float4 o0 = make_float4(vals[0], vals[1], vals[2], vals[3]);
            float4 o1 = make_float4(vals[4], vals[5], vals[6], vals[7]);
            *reinterpret_cast<float4*>(Cp) = o0;
            *reinterpret_cast<float4*>(Cp + 4) = o1;
        }
    }
}

// ---------------- host launch ----------------------------------------------------
static void launch_gemm(const float* A, const float* W, const float* bias, float* C,
                        int M, int N, int K, bool gelu_act, bool accum) {
    dim3 grid((M + BM - 1) / BM, N / BN);
    if (gelu_act)       gemm_k<true, false><<<grid, 256>>>(A, W, bias, C, M, N, K);
    else if (accum)     gemm_k<false, true><<<grid, 256>>>(A, W, bias, C, M, N, K);
    else                gemm_k<false, false><<<grid, 256>>>(A, W, bias, C, M, N, K);
}

extern "C" void kernel_launch(void* const* d_in, const int* in_sizes, int n_in,
                              void* d_out, int out_size) {
    const float* pos      = (const float*)d_in[0];
    const float* vel      = (const float*)d_in[1];
    const float* charges  = (const float*)d_in[2];
    const int*   batch    = (const int*)d_in[3];
    const int*   eidx     = (const int*)d_in[4];
    const float* grid0    = (const float*)d_in[5];
    const float* R        = (const float*)d_in[6];
    const float* W_basis1 = (const float*)d_in[7];
    const float* b_basis1 = (const float*)d_in[8];
    const float* W_basis2 = (const float*)d_in[9];
    const float* b_basis2 = (const float*)d_in[10];
    const float* W_fbasis1 = (const float*)d_in[11];
    const float* b_fbasis1 = (const float*)d_in[12];
    const float* W_fbasis2 = (const float*)d_in[13];
    const float* b_fbasis2 = (const float*)d_in[14];
    const float* W_embed  = (const float*)d_in[15];
    const float* W_conv   = (const float*)d_in[16];
    const float* W_fiber  = (const float*)d_in[17];
    const float* b_conv   = (const float*)d_in[18];
    const float* ln_gamma = (const float*)d_in[19];
    const float* ln_beta  = (const float*)d_in[20];
    const float* W_ff1    = (const float*)d_in[21];
    const float* b_ff1    = (const float*)d_in[22];
    const float* W_ff2    = (const float*)d_in[23];
    const float* b_ff2    = (const float*)d_in[24];
    const float* W_ro1    = (const float*)d_in[25];
    const float* b_ro1    = (const float*)d_in[26];
    const float* W_ro2    = (const float*)d_in[27];
    const float* b_ro2    = (const float*)d_in[28];
    float* out = (float*)d_out;

    float *bufA, *basis, *x, *x1, *x2, *ffh, *eip, *fip, *fh1, *fbasis, *fk, *gsum;
    cudaGetSymbolAddress((void**)&bufA,  g_bufA);
    cudaGetSymbolAddress((void**)&basis, g_basis);
    cudaGetSymbolAddress((void**)&x,     g_x);
    cudaGetSymbolAddress((void**)&x1,    g_x1);
    cudaGetSymbolAddress((void**)&x2,    g_x2);
    cudaGetSymbolAddress((void**)&ffh,   g_ffh);
    cudaGetSymbolAddress((void**)&eip,   g_eipoly);
    cudaGetSymbolAddress((void**)&fip,   g_fipoly);
    cudaGetSymbolAddress((void**)&fh1,   g_fh1);
    cudaGetSymbolAddress((void**)&fbasis,g_fbasis);
    cudaGetSymbolAddress((void**)&fk,    g_fk);
    cudaGetSymbolAddress((void**)&gsum,  g_gsum);

    // graph statistics + rotated grids
    k_zero<<<(Bb * 4 + 255) / 256, 256>>>(gsum, Bb * 4);
    k_gsum<<<(Nn + 255) / 256, 256>>>(pos, batch);
    k_grid_node<<<(Nn * NGg + 255) / 256, 256>>>(batch, grid0, R);

    // edge basis MLP: 600k rows
    k_eipoly<<<(EROWS + 255) / 256, 256>>>(pos, charges, eidx);
    launch_gemm(eip,  W_basis1, b_basis1, bufA,  EROWS, Hh, 12, true, false);
    launch_gemm(bufA, W_basis2, b_basis2, basis, EROWS, BDd, Hh, true, false);

    // fiber basis MLP: 144 rows
    k_fipoly<<<1, 256>>>(grid0);
    k_small_gemm<<<(NGg * NGg * Hh + 255) / 256, 256>>>(fip, W_fbasis1, b_fbasis1, fh1,
                                                        NGg * NGg, Hh, 2, 1);
    k_small_gemm<<<(NGg * NGg * BDd + 255) / 256, 256>>>(fh1, W_fbasis2, b_fbasis2, fbasis,
                                                         NGg * NGg, BDd, Hh, 1);

    // node embedding
    k_embed<<<NROWS, Hh>>>(pos, vel, charges, batch, W_embed);

    for (int l = 0; l < Ll; l++) {
        // kern = basis @ W_conv[l]  (600k x 128 x 128)
        launch_gemm(basis, W_conv + (size_t)l * BDd * Hh, nullptr, bufA, EROWS, Hh, BDd,
                    false, false);
        // x1 = segment_sum(x[src] * kern, dst)
        k_zero<<<(NROWS * Hh + 255) / 256, 256>>>(x1, NROWS * Hh);
        k_scatter<<<(Ee * NGg * (Hh / 4) + 255) / 256, 256>>>(eidx);
        // fk = fiber_basis @ W_fiber[l]
        k_small_gemm<<<(NGg * NGg * Hh + 255) / 256, 256>>>(
            fbasis, W_fiber + (size_t)l * BDd * Hh, nullptr, fk, NGg * NGg, Hh, BDd, 0);
        // x2 = einsum/NG + b_conv, LayerNorm -> g_x2
        k_fiber_ln<<<NROWS, Hh>>>(b_conv + l * Hh, ln_gamma + l * Hh, ln_beta + l * Hh);
        // FF: x += W_ff2 @ gelu(W_ff1 @ h)
        launch_gemm(x2, W_ff1 + (size_t)l * Hh * 4 * Hh, b_ff1 + l * 4 * Hh, ffh,
                    NROWS, 4 * Hh, Hh, true, false);
        launch_gemm(ffh, W_ff2 + (size_t)l * 4 * Hh * Hh, b_ff2 + l * Hh, x,
                    NROWS, Hh, 4 * Hh, false, true);
    }

    // readout
    launch_gemm(x, W_ro1, b_ro1, ffh, NROWS, Hh, Hh, true, false);
    k_output<<<Nn, Hh>>>(W_ro2, b_ro2, out);
}